// round 5
// baseline (speedup 1.0000x reference)
#include <cuda_runtime.h>

#define I_DIM 28
#define H_DIM 64
#define T_DIM 128
#define B_DIM 4096
#define OUT_DIM 10
#define TI (T_DIM * I_DIM)          // 3584
#define ROWS 28                     // batch rows per CTA (14 real pairs)
#define THREADS 256
#define NBLOCKS 147                 // one CTA per SM
#define NSLOT 16                    // 14 real pair-slots + 2 dummy

typedef unsigned long long u64;

// ---- f32x2 packed math ----
__device__ __forceinline__ u64 pack2(float lo, float hi) {
    u64 r; asm("mov.b64 %0, {%1, %2};" : "=l"(r) : "f"(lo), "f"(hi)); return r;
}
__device__ __forceinline__ void unpack2(u64 v, float& lo, float& hi) {
    asm("mov.b64 {%0, %1}, %2;" : "=f"(lo), "=f"(hi) : "l"(v));
}
__device__ __forceinline__ u64 ffma2(u64 a, u64 b, u64 c) {
    u64 d; asm("fma.rn.f32x2 %0, %1, %2, %3;" : "=l"(d) : "l"(a), "l"(b), "l"(c)); return d;
}
// ---- PROVEN activations (rel_err 2.9e-7 end-to-end; tanh.approx is NOT safe here) ----
__device__ __forceinline__ float rcpa(float x) { float r; asm("rcp.approx.f32 %0, %1;" : "=f"(r) : "f"(x)); return r; }
__device__ __forceinline__ float ex2a(float x) { float r; asm("ex2.approx.f32 %0, %1;" : "=f"(r) : "f"(x)); return r; }
__device__ __forceinline__ float sigm(float x)  { return rcpa(1.0f + ex2a(-1.4426950408889634f * x)); }
__device__ __forceinline__ float tanh_(float x) { return fmaf(2.0f, rcpa(1.0f + ex2a(-2.8853900817779268f * x)), -1.0f); }

// smem (u64 units):
//   sWhh2 : 64 k-rows x 256 u64  = 131072 B   row = [{wi,wf}[64] | {wg,wo}[64]] duplicated-f32x2
//   sWih2 : 28 i-rows x 256 u64  =  57344 B
//   sb2   : 64 x 4 u64           =   2048 B
//   shT   : 2 x 64 x 16 u64      =  16384 B   (double-buffered h, [k][slot])
//   sxT   : 2 x 28 x 16 u64      =   7168 B   (double-buffered x_t, [i][slot])
#define SMEM_BYTES (131072 + 57344 + 2048 + 16384 + 7168)   // 214016 < 232448

__global__ void __launch_bounds__(THREADS, 1)
lstm_kernel(const float* __restrict__ x,
            const float* __restrict__ W_ih,
            const float* __restrict__ W_hh,
            const float* __restrict__ b_ih,
            const float* __restrict__ b_hh,
            const float* __restrict__ W_out,
            const float* __restrict__ b_out,
            float* __restrict__ out)
{
    extern __shared__ u64 smem_u[];
    u64* sWhh2 = smem_u;                        // [k][256]
    u64* sWih2 = sWhh2 + H_DIM * 256;           // [i][256]
    u64* sb2   = sWih2 + I_DIM * 256;           // [u][4]
    u64* shT   = sb2 + H_DIM * 4;               // 2 x [k][16]
    u64* sxT   = shT + 2 * H_DIM * NSLOT;       // 2 x [i][16]

    const int tid  = threadIdx.x;
    const int w    = tid >> 5;
    const int lane = tid & 31;
    const int ug   = lane & 7;
    const int pg   = lane >> 3;                 // pair-group: slots [4pg..4pg+4)
    const int u    = (w << 3) | ug;             // hidden unit 0..63
    const int sb0  = pg << 2;                   // first slot
    const int row0 = blockIdx.x * ROWS;

    // ---- weight staging: duplicated f32x2, dedup-friendly layout ----
    for (int idx = tid; idx < I_DIM * H_DIM; idx += THREADS) {
        int uu = idx & 63, ii = idx >> 6;
        u64* dst = sWih2 + ii * 256;
        dst[2 * uu]           = pack2(W_ih[uu * I_DIM + ii],         W_ih[uu * I_DIM + ii]);
        dst[2 * uu + 1]       = pack2(W_ih[(64 + uu) * I_DIM + ii],  W_ih[(64 + uu) * I_DIM + ii]);
        dst[128 + 2 * uu]     = pack2(W_ih[(128 + uu) * I_DIM + ii], W_ih[(128 + uu) * I_DIM + ii]);
        dst[128 + 2 * uu + 1] = pack2(W_ih[(192 + uu) * I_DIM + ii], W_ih[(192 + uu) * I_DIM + ii]);
    }
    for (int idx = tid; idx < H_DIM * H_DIM; idx += THREADS) {
        int uu = idx & 63, kk = idx >> 6;
        u64* dst = sWhh2 + kk * 256;
        dst[2 * uu]           = pack2(W_hh[uu * H_DIM + kk],         W_hh[uu * H_DIM + kk]);
        dst[2 * uu + 1]       = pack2(W_hh[(64 + uu) * H_DIM + kk],  W_hh[(64 + uu) * H_DIM + kk]);
        dst[128 + 2 * uu]     = pack2(W_hh[(128 + uu) * H_DIM + kk], W_hh[(128 + uu) * H_DIM + kk]);
        dst[128 + 2 * uu + 1] = pack2(W_hh[(192 + uu) * H_DIM + kk], W_hh[(192 + uu) * H_DIM + kk]);
    }
    if (tid < H_DIM) {
        u64* d = sb2 + tid * 4;
        float v0 = b_ih[tid]       + b_hh[tid];
        float v1 = b_ih[64 + tid]  + b_hh[64 + tid];
        float v2 = b_ih[128 + tid] + b_hh[128 + tid];
        float v3 = b_ih[192 + tid] + b_hh[192 + tid];
        d[0] = pack2(v0, v0); d[1] = pack2(v1, v1);
        d[2] = pack2(v2, v2); d[3] = pack2(v3, v3);
    }
    // h buffer 0 = 0; both x buffers = 0 (covers dummy slots forever)
    for (int idx = tid; idx < H_DIM * NSLOT; idx += THREADS) shT[idx] = 0ull;
    for (int idx = tid; idx < 2 * I_DIM * NSLOT; idx += THREADS) sxT[idx] = 0ull;

    // ---- per-thread x-load assignments (784 = 28 rows * 28 elems) ----
    int er[4], ei[4]; bool ev[4], gv[4]; const float* xp[4];
    #pragma unroll
    for (int j = 0; j < 4; ++j) {
        int e = tid + j * THREADS;
        ev[j] = (e < ROWS * I_DIM);
        int ec = ev[j] ? e : 0;
        er[j] = ec / I_DIM;
        ei[j] = ec - er[j] * I_DIM;
        gv[j] = ev[j] && (row0 + er[j] < B_DIM);
        xp[j] = x + (size_t)(gv[j] ? (row0 + er[j]) : 0) * TI + ei[j];
    }
    __syncthreads();   // zeroed x buffers visible before staging writes
    {
        float* x0 = (float*)sxT;   // rows of 16 u64 = 32 floats
        #pragma unroll
        for (int j = 0; j < 4; ++j)
            if (ev[j]) x0[ei[j] * 32 + er[j]] = gv[j] ? xp[j][0] : 0.0f;
    }

    float cc[8];
    #pragma unroll
    for (int p = 0; p < 8; ++p) cc[p] = 0.0f;

    __syncthreads();   // weights + biases + h0 + x0 visible
    u64 bi, bf, bg, bo;
    {
        ulonglong2 b01 = *(const ulonglong2*)(sb2 + u * 4);
        ulonglong2 b23 = *(const ulonglong2*)(sb2 + u * 4 + 2);
        bi = b01.x; bf = b01.y; bg = b23.x; bo = b23.y;
    }

    for (int t = 0; t < T_DIM; ++t) {
        const int cur = t & 1, nxt = cur ^ 1;
        const u64* hcur = shT + cur * (H_DIM * NSLOT);
        u64*       hnxt = shT + nxt * (H_DIM * NSLOT);
        const u64* xcur = sxT + cur * (I_DIM * NSLOT);
        float*     xnx  = (float*)(sxT + nxt * (I_DIM * NSLOT));

        // prefetch next timestep's x (hidden under FMAs)
        float xn[4];
        if (t + 1 < T_DIM) {
            #pragma unroll
            for (int j = 0; j < 4; ++j)
                xn[j] = gv[j] ? xp[j][(t + 1) * I_DIM] : 0.0f;
        }

        u64 a0[4], a1[4], a2[4], a3[4];
        #pragma unroll
        for (int j = 0; j < 4; ++j) { a0[j] = bi; a1[j] = bf; a2[j] = bg; a3[j] = bo; }

        // input projection: 28 x (4 LDS.128 + 16 FFMA2)
        #pragma unroll 4
        for (int i = 0; i < I_DIM; ++i) {
            const u64* wr = sWih2 + (i << 8);
            ulonglong2 wif = *(const ulonglong2*)(wr + 2 * u);
            ulonglong2 wgo = *(const ulonglong2*)(wr + 128 + 2 * u);
            const u64* xr = xcur + (i << 4) + sb0;
            ulonglong2 v01 = *(const ulonglong2*)(xr);
            ulonglong2 v23 = *(const ulonglong2*)(xr + 2);
            u64 v[4] = { v01.x, v01.y, v23.x, v23.y };
            #pragma unroll
            for (int j = 0; j < 4; ++j) {
                a0[j] = ffma2(wif.x, v[j], a0[j]);
                a1[j] = ffma2(wif.y, v[j], a1[j]);
                a2[j] = ffma2(wgo.x, v[j], a2[j]);
                a3[j] = ffma2(wgo.y, v[j], a3[j]);
            }
        }
        // recurrent projection: 64 x (4 LDS.128 + 16 FFMA2)
        #pragma unroll 4
        for (int k = 0; k < H_DIM; ++k) {
            const u64* wr = sWhh2 + (k << 8);
            ulonglong2 wif = *(const ulonglong2*)(wr + 2 * u);
            ulonglong2 wgo = *(const ulonglong2*)(wr + 128 + 2 * u);
            const u64* hr = hcur + (k << 4) + sb0;
            ulonglong2 v01 = *(const ulonglong2*)(hr);
            ulonglong2 v23 = *(const ulonglong2*)(hr + 2);
            u64 v[4] = { v01.x, v01.y, v23.x, v23.y };
            #pragma unroll
            for (int j = 0; j < 4; ++j) {
                a0[j] = ffma2(wif.x, v[j], a0[j]);
                a1[j] = ffma2(wif.y, v[j], a1[j]);
                a2[j] = ffma2(wgo.x, v[j], a2[j]);
                a3[j] = ffma2(wgo.y, v[j], a3[j]);
            }
        }

        // activations + state update + h write into next buffer
        u64 hn[4];
        #pragma unroll
        for (int j = 0; j < 4; ++j) {
            float v0, v1;
            unpack2(a0[j], v0, v1); float i0 = sigm(v0),  i1 = sigm(v1);
            unpack2(a1[j], v0, v1); float f0 = sigm(v0),  f1 = sigm(v1);
            unpack2(a2[j], v0, v1); float g0 = tanh_(v0), g1 = tanh_(v1);
            unpack2(a3[j], v0, v1); float o0 = sigm(v0),  o1 = sigm(v1);
            float c0 = fmaf(f0, cc[2 * j],     i0 * g0);
            float c1 = fmaf(f1, cc[2 * j + 1], i1 * g1);
            cc[2 * j] = c0; cc[2 * j + 1] = c1;
            hn[j] = pack2(o0 * tanh_(c0), o1 * tanh_(c1));
        }
        {
            u64* hd = hnxt + (u << 4) + sb0;
            *(ulonglong2*)(hd)     = make_ulonglong2(hn[0], hn[1]);
            *(ulonglong2*)(hd + 2) = make_ulonglong2(hn[2], hn[3]);
        }
        // stage next x into the next buffer
        if (t + 1 < T_DIM) {
            #pragma unroll
            for (int j = 0; j < 4; ++j)
                if (ev[j]) xnx[ei[j] * 32 + er[j]] = xn[j];
        }
        __syncthreads();   // single barrier per step
    }

    // ---- output head: T=128 even -> final h in buffer 0; h[k][r] at float k*32+r ----
    const float* hf = (const float*)shT;
    for (int e = tid; e < ROWS * OUT_DIM; e += THREADS) {
        int r = e / OUT_DIM, o = e - r * OUT_DIM;
        if (row0 + r < B_DIM) {
            float a = b_out[o];
            #pragma unroll
            for (int k = 0; k < H_DIM; ++k)
                a = fmaf(hf[k * 32 + r], W_out[o * H_DIM + k], a);
            out[(size_t)(row0 + r) * OUT_DIM + o] = a;
        }
    }
}

extern "C" void kernel_launch(void* const* d_in, const int* in_sizes, int n_in,
                              void* d_out, int out_size) {
    const float* x     = (const float*)d_in[0];
    const float* W_ih  = (const float*)d_in[1];
    const float* W_hh  = (const float*)d_in[2];
    const float* b_ih  = (const float*)d_in[3];
    const float* b_hh  = (const float*)d_in[4];
    const float* W_out = (const float*)d_in[5];
    const float* b_out = (const float*)d_in[6];
    float* out = (float*)d_out;

    cudaFuncSetAttribute(lstm_kernel, cudaFuncAttributeMaxDynamicSharedMemorySize, SMEM_BYTES);
    lstm_kernel<<<NBLOCKS, THREADS, SMEM_BYTES>>>(x, W_ih, W_hh, b_ih, b_hh, W_out, b_out, out);
}

// round 6
// speedup vs baseline: 1.2984x; 1.2984x over previous
#include <cuda_runtime.h>

#define I_DIM 28
#define H_DIM 64
#define T_DIM 128
#define B_DIM 4096
#define OUT_DIM 10
#define TI (T_DIM * I_DIM)          // 3584
#define ROWS 28                     // batch rows per CTA (14 pairs)
#define THREADS 256
#define NBLOCKS 147                 // one CTA per SM
#define ST 18                       // pair-row stride in u64 (144B: 16B-aligned, conflict-free)
#define ST_F 36

typedef unsigned long long u64;

__device__ __forceinline__ u64 pack2(float lo, float hi) {
    u64 r; asm("mov.b64 %0, {%1, %2};" : "=l"(r) : "f"(lo), "f"(hi)); return r;
}
__device__ __forceinline__ void unpack2(u64 v, float& lo, float& hi) {
    asm("mov.b64 {%0, %1}, %2;" : "=f"(lo), "=f"(hi) : "l"(v));
}
__device__ __forceinline__ u64 ffma2(u64 a, u64 b, u64 c) {
    u64 d; asm("fma.rn.f32x2 %0, %1, %2, %3;" : "=l"(d) : "l"(a), "l"(b), "l"(c)); return d;
}
// ---- PROVEN activations (end-to-end rel_err 2.9e-7; tanh.approx is NOT safe here) ----
__device__ __forceinline__ float rcpa(float x) { float r; asm("rcp.approx.f32 %0, %1;" : "=f"(r) : "f"(x)); return r; }
__device__ __forceinline__ float ex2a(float x) { float r; asm("ex2.approx.f32 %0, %1;" : "=f"(r) : "f"(x)); return r; }
__device__ __forceinline__ float sigm(float x)  { return rcpa(1.0f + ex2a(-1.4426950408889634f * x)); }
__device__ __forceinline__ float tanh_(float x) { return fmaf(2.0f, rcpa(1.0f + ex2a(-2.8853900817779268f * x)), -1.0f); }

// smem (bytes):
//   sWhh 64*64 float4 = 65536   [k][u] -> {wi,wf,wg,wo}
//   sWih 28*64 float4 = 28672
//   sb   64    float4 = 1024
//   shT  2 x 64*18 u64 = 18432  (double-buffered h pairs, row stride 18)
//   sxT  2 x 28*18 u64 = 8064   (double-buffered x pairs)
#define SMEM_BYTES (65536 + 28672 + 1024 + 18432 + 8064)   // 121728

// GEMM accumulate over NR reduction rows. Values fetched as u64-pair broadcasts
// (ulonglong2 where alignment allows -> 1 wavefront each).
template<int NR, int NP, int PB>
__device__ __forceinline__ void accum(const float4* __restrict__ Wm,
                                      const u64* __restrict__ vbuf,
                                      int u, u64* a0, u64* a1, u64* a2, u64* a3)
{
    #pragma unroll 4
    for (int r = 0; r < NR; ++r) {
        float4 w = Wm[(r << 6) + u];
        u64 wi = pack2(w.x, w.x), wf = pack2(w.y, w.y);
        u64 wg = pack2(w.z, w.z), wo = pack2(w.w, w.w);
        const u64* vr = vbuf + r * ST;
        u64 v[NP];
        if constexpr (NP == 4) {
            ulonglong2 p0 = *(const ulonglong2*)(vr + PB);
            ulonglong2 p1 = *(const ulonglong2*)(vr + PB + 2);
            v[0] = p0.x; v[1] = p0.y; v[2] = p1.x; v[3] = p1.y;
        } else if constexpr (PB == 8) {
            ulonglong2 p0 = *(const ulonglong2*)(vr + 8);
            v[0] = p0.x; v[1] = p0.y; v[2] = vr[10];
        } else {  // PB == 11
            v[0] = vr[11];
            ulonglong2 p1 = *(const ulonglong2*)(vr + 12);
            v[1] = p1.x; v[2] = p1.y;
        }
        #pragma unroll
        for (int j = 0; j < NP; ++j) {
            a0[j] = ffma2(wi, v[j], a0[j]);
            a1[j] = ffma2(wf, v[j], a1[j]);
            a2[j] = ffma2(wg, v[j], a2[j]);
            a3[j] = ffma2(wo, v[j], a3[j]);
        }
    }
}

template<int NP, int PB>
__device__ __forceinline__ void store_h(u64* __restrict__ hrow, const u64* hn)
{
    if constexpr (NP == 4) {
        *(ulonglong2*)(hrow + PB)     = make_ulonglong2(hn[0], hn[1]);
        *(ulonglong2*)(hrow + PB + 2) = make_ulonglong2(hn[2], hn[3]);
    } else if constexpr (PB == 8) {
        *(ulonglong2*)(hrow + 8) = make_ulonglong2(hn[0], hn[1]);
        hrow[10] = hn[2];
    } else {  // PB == 11
        hrow[11] = hn[0];
        *(ulonglong2*)(hrow + 12) = make_ulonglong2(hn[1], hn[2]);
    }
}

// Pipelined mainloop: recurrent(t) -> epilogue(t) -> input-proj(t+1) -> barrier.
template<int NP, int PB>
__device__ __forceinline__ void mainloop(
    const float4* __restrict__ sWih, const float4* __restrict__ sWhh,
    u64* __restrict__ shT, u64* __restrict__ sxT,
    int u, u64 bi, u64 bf, u64 bg, u64 bo,
    const float* const* xp, const bool* gv, const bool* ev,
    const int* er, const int* ei)
{
    u64 a0[NP], a1[NP], a2[NP], a3[NP];
    float cc[2 * NP];
    #pragma unroll
    for (int j = 0; j < NP; ++j) {
        a0[j] = bi; a1[j] = bf; a2[j] = bg; a3[j] = bo;
        cc[2 * j] = 0.0f; cc[2 * j + 1] = 0.0f;
    }
    // input projection for t = 0 (x(0) already staged in xT buffer 0)
    accum<I_DIM, NP, PB>(sWih, sxT, u, a0, a1, a2, a3);

    for (int t = 0; t < T_DIM; ++t) {
        const bool pf = (t + 2 < T_DIM);
        // early global prefetch of x(t+2) (long latency, hidden under FMAs)
        float xn[4];
        if (pf) {
            #pragma unroll
            for (int j = 0; j < 4; ++j)
                xn[j] = gv[j] ? xp[j][(t + 2) * I_DIM] : 0.0f;
        }

        // recurrent projection on h(t)
        accum<H_DIM, NP, PB>(sWhh, shT + (t & 1) * (H_DIM * ST), u, a0, a1, a2, a3);

        // epilogue: gates -> c, h(t+1)
        u64 hn[NP];
        #pragma unroll
        for (int j = 0; j < NP; ++j) {
            float v0, v1;
            unpack2(a0[j], v0, v1); float i0 = sigm(v0),  i1 = sigm(v1);
            unpack2(a1[j], v0, v1); float f0 = sigm(v0),  f1 = sigm(v1);
            unpack2(a2[j], v0, v1); float g0 = tanh_(v0), g1 = tanh_(v1);
            unpack2(a3[j], v0, v1); float o0 = sigm(v0),  o1 = sigm(v1);
            float c0 = fmaf(f0, cc[2 * j],     i0 * g0);
            float c1 = fmaf(f1, cc[2 * j + 1], i1 * g1);
            cc[2 * j] = c0; cc[2 * j + 1] = c1;
            hn[j] = pack2(o0 * tanh_(c0), o1 * tanh_(c1));
        }
        store_h<NP, PB>(shT + ((t + 1) & 1) * (H_DIM * ST) + u * ST, hn);

        // input projection for t+1 (independent of h-write; its FFMA2s hide the
        // epilogue MUFU chains). Reads x buffer staged two iterations ago.
        if (t < T_DIM - 1) {
            #pragma unroll
            for (int j = 0; j < NP; ++j) { a0[j] = bi; a1[j] = bf; a2[j] = bg; a3[j] = bo; }
            accum<I_DIM, NP, PB>(sWih, sxT + ((t + 1) & 1) * (I_DIM * ST), u, a0, a1, a2, a3);
        }

        // stage x(t+2) into the buffer not being read this or next iteration
        if (pf) {
            float* xd = (float*)(sxT + (t & 1) * (I_DIM * ST));
            #pragma unroll
            for (int j = 0; j < 4; ++j)
                if (ev[j]) xd[ei[j] * ST_F + er[j]] = xn[j];
        }
        __syncthreads();
    }
}

__global__ void __launch_bounds__(THREADS, 1)
lstm_kernel(const float* __restrict__ x,
            const float* __restrict__ W_ih,
            const float* __restrict__ W_hh,
            const float* __restrict__ b_ih,
            const float* __restrict__ b_hh,
            const float* __restrict__ W_out,
            const float* __restrict__ b_out,
            float* __restrict__ out)
{
    extern __shared__ float smem_f[];
    float4* sWhh = (float4*)smem_f;
    float4* sWih = sWhh + H_DIM * H_DIM;
    float4* sb   = sWih + I_DIM * H_DIM;
    u64*    shT  = (u64*)(sb + H_DIM);        // 2 x [k][ST]
    u64*    sxT  = shT + 2 * H_DIM * ST;      // 2 x [i][ST]

    const int tid = threadIdx.x;
    const int u   = tid & 63;
    const int q   = tid >> 6;                 // pair-group; SMSP-balanced 4/4/3/3
    const int row0 = blockIdx.x * ROWS;

    // ---- weight staging (gate-interleaved float4, [row][u]) ----
    for (int idx = tid; idx < I_DIM * H_DIM; idx += THREADS) {
        int uu = idx & 63, ii = idx >> 6;
        sWih[ii * H_DIM + uu] = make_float4(
            W_ih[uu * I_DIM + ii],
            W_ih[(64 + uu) * I_DIM + ii],
            W_ih[(128 + uu) * I_DIM + ii],
            W_ih[(192 + uu) * I_DIM + ii]);
    }
    for (int idx = tid; idx < H_DIM * H_DIM; idx += THREADS) {
        int uu = idx & 63, kk = idx >> 6;
        sWhh[kk * H_DIM + uu] = make_float4(
            W_hh[uu * H_DIM + kk],
            W_hh[(64 + uu) * H_DIM + kk],
            W_hh[(128 + uu) * H_DIM + kk],
            W_hh[(192 + uu) * H_DIM + kk]);
    }
    if (tid < H_DIM) {
        sb[tid] = make_float4(b_ih[tid] + b_hh[tid],
                              b_ih[64 + tid] + b_hh[64 + tid],
                              b_ih[128 + tid] + b_hh[128 + tid],
                              b_ih[192 + tid] + b_hh[192 + tid]);
    }
    // h(0) = 0 in buffer 0 (padding included, one-time)
    for (int idx = tid; idx < H_DIM * ST; idx += THREADS) shT[idx] = 0ull;

    // ---- per-thread x assignments (784 = 28 rows * 28 elems) ----
    int er[4], ei[4]; bool ev[4], gv[4]; const float* xp[4];
    #pragma unroll
    for (int j = 0; j < 4; ++j) {
        int e = tid + j * THREADS;
        ev[j] = (e < ROWS * I_DIM);
        int ec = ev[j] ? e : 0;
        er[j] = ec / I_DIM;
        ei[j] = ec - er[j] * I_DIM;
        gv[j] = ev[j] && (row0 + er[j] < B_DIM);
        xp[j] = x + (size_t)(gv[j] ? (row0 + er[j]) : 0) * TI + ei[j];
    }
    // stage x(0) -> buffer 0, x(1) -> buffer 1
    {
        float* x0 = (float*)sxT;
        float* x1 = (float*)(sxT + I_DIM * ST);
        #pragma unroll
        for (int j = 0; j < 4; ++j) {
            if (ev[j]) {
                x0[ei[j] * ST_F + er[j]] = gv[j] ? xp[j][0] : 0.0f;
                x1[ei[j] * ST_F + er[j]] = gv[j] ? xp[j][I_DIM] : 0.0f;
            }
        }
    }

    __syncthreads();   // weights + biases + h0 + x0/x1 visible
    float4 bv = sb[u];
    u64 bi = pack2(bv.x, bv.x), bf = pack2(bv.y, bv.y);
    u64 bg = pack2(bv.z, bv.z), bo = pack2(bv.w, bv.w);

    // pair-slot split: q0 [0,4) q1 [4,8) q2 [8,11) q3 [11,14)  (7 pairs per SMSP)
    switch (q) {
        case 0: mainloop<4, 0 >(sWih, sWhh, shT, sxT, u, bi, bf, bg, bo, xp, gv, ev, er, ei); break;
        case 1: mainloop<4, 4 >(sWih, sWhh, shT, sxT, u, bi, bf, bg, bo, xp, gv, ev, er, ei); break;
        case 2: mainloop<3, 8 >(sWih, sWhh, shT, sxT, u, bi, bf, bg, bo, xp, gv, ev, er, ei); break;
        default: mainloop<3, 11>(sWih, sWhh, shT, sxT, u, bi, bf, bg, bo, xp, gv, ev, er, ei); break;
    }

    // ---- output head: T=128 even -> final h in buffer 0; h[k][r] at float k*ST_F + r ----
    const float* hf = (const float*)shT;
    for (int e = tid; e < ROWS * OUT_DIM; e += THREADS) {
        int r = e / OUT_DIM, o = e - r * OUT_DIM;
        if (row0 + r < B_DIM) {
            float a = b_out[o];
            #pragma unroll
            for (int k = 0; k < H_DIM; ++k)
                a = fmaf(hf[k * ST_F + r], W_out[o * H_DIM + k], a);
            out[(size_t)(row0 + r) * OUT_DIM + o] = a;
        }
    }
}

extern "C" void kernel_launch(void* const* d_in, const int* in_sizes, int n_in,
                              void* d_out, int out_size) {
    const float* x     = (const float*)d_in[0];
    const float* W_ih  = (const float*)d_in[1];
    const float* W_hh  = (const float*)d_in[2];
    const float* b_ih  = (const float*)d_in[3];
    const float* b_hh  = (const float*)d_in[4];
    const float* W_out = (const float*)d_in[5];
    const float* b_out = (const float*)d_in[6];
    float* out = (float*)d_out;

    cudaFuncSetAttribute(lstm_kernel, cudaFuncAttributeMaxDynamicSharedMemorySize, SMEM_BYTES);
    lstm_kernel<<<NBLOCKS, THREADS, SMEM_BYTES>>>(x, W_ih, W_hh, b_ih, b_hh, W_out, b_out, out);
}